// round 13
// baseline (speedup 1.0000x reference)
#include <cuda_runtime.h>
#include <cstdint>

#define N_SEQ 8192
#define DH    512
#define DE    128
#define TMAX  80
#define G3    1536

#define PADM 68                        // A-tile float stride (64m + pad, 16B-aligned, even)
#define WPAD 36                        // W-tile float stride (16B-aligned, even)
#define A_BYTES (32 * PADM * 4)        // 8704
#define W_BYTES (96 * WPAD * 4)        // 13824
#define BUF_BYTES (A_BYTES + W_BYTES)  // 22528
#define GRU_SMEM (3 * BUF_BYTES)       // 67584 (triple buffer, 3 blocks/SM)

#define HPADM 132                          // head A-tile stride (128 rows)
#define HA_BYTES (32 * HPADM * 4)          // 16896
#define HW_BYTES (64 * WPAD * 4)           // 9216
#define HBUF_BYTES (HA_BYTES + HW_BYTES)   // 26112
#define HEAD_SMEM (2 * HBUF_BYTES)         // 52224

typedef unsigned long long u64;

// ---------------- device-global state (module-static, no runtime allocation) ----------------
// COLUMN-MAJOR hidden state: [buf][layer][feature][row] so A-tiles are cp.async-contiguous.
__device__ __align__(16) float g_H[2][3][DH][N_SEQ];
__device__ __align__(16) float g_X0[DE][N_SEQ];        // embedded previous token, col-major
__device__ int g_eos[N_SEQ];
__device__ int g_first[N_SEQ];
__device__ int g_tdone[N_SEQ / 64];

// ---------------- helpers ----------------
__device__ __forceinline__ uint32_t smem_u32(const void* p) {
    uint32_t a;
    asm("{ .reg .u64 t; cvta.to.shared.u64 t, %1; cvt.u32.u64 %0, t; }" : "=r"(a) : "l"(p));
    return a;
}
__device__ __forceinline__ u64 pack2(float x) {
    u64 r;
    asm("mov.b64 %0, {%1, %1};" : "=l"(r) : "f"(x));
    return r;
}
__device__ __forceinline__ float2 unpack2(u64 v) {
    float lo, hi;
    asm("mov.b64 {%0, %1}, %2;" : "=f"(lo), "=f"(hi) : "l"(v));
    return make_float2(lo, hi);
}
#define FMA2(acc, a, w) \
    asm("fma.rn.f32x2 %0, %1, %2, %0;" : "+l"(acc) : "l"(a), "l"(w))

__device__ __forceinline__ void cp16(uint32_t dst, const void* src) {
    asm volatile("cp.async.cg.shared.global [%0], [%1], 16;" :: "r"(dst), "l"(src));
}
#define CP_COMMIT() asm volatile("cp.async.commit_group;" ::: "memory")
#define CP_WAIT0()  asm volatile("cp.async.wait_group 0;" ::: "memory")
#define CP_WAIT1()  asm volatile("cp.async.wait_group 1;" ::: "memory")

// ---------------- init: eos=0, X_gen col0 = SOS, X0 = emb[SOS] (col-major) ----------------
__global__ void init_kernel(const float* __restrict__ emb, float* __restrict__ Xgen) {
    int t = blockIdx.x * 256 + threadIdx.x;   // N_SEQ*32 threads
    int row = t >> 5, lane = t & 31;
    if (row >= N_SEQ) return;
    float4 e = ((const float4*)(emb + 1 * DE))[lane];
    g_X0[lane * 4 + 0][row] = e.x;
    g_X0[lane * 4 + 1][row] = e.y;
    g_X0[lane * 4 + 2][row] = e.z;
    g_X0[lane * 4 + 3][row] = e.w;
    if (lane == 0) {
        g_eos[row]   = 0;
        g_first[row] = 0;
        Xgen[row * TMAX] = 1.0f;   // SOS (output buffer is float32)
        if (row < N_SEQ / 64) g_tdone[row] = 0;
    }
}

// ---------------- h0 = Z @ z2h_w^T + b, replicated to 3 layers of buffer 0 (col-major) ----------------
__global__ void __launch_bounds__(256)
h0_kernel(const float* __restrict__ Z, const float* __restrict__ z2h_w,
          const float* __restrict__ z2h_b) {
    __shared__ __align__(16) float Zs[32][DE];
    __shared__ __align__(16) float Ws[32][DE + 1];
    const int m0 = blockIdx.x * 32, j0 = blockIdx.y * 32;
    const int tid = threadIdx.x;
    for (int i = tid; i < 32 * (DE / 4); i += 256) {
        int r = i >> 5, c = i & 31;
        float4 z4 = ((const float4*)(Z + (size_t)(m0 + r) * DE))[c];
        Zs[r][c * 4 + 0] = z4.x; Zs[r][c * 4 + 1] = z4.y;
        Zs[r][c * 4 + 2] = z4.z; Zs[r][c * 4 + 3] = z4.w;
        float4 w4 = ((const float4*)(z2h_w + (size_t)(j0 + r) * DE))[c];
        Ws[r][c * 4 + 0] = w4.x; Ws[r][c * 4 + 1] = w4.y;
        Ws[r][c * 4 + 2] = w4.z; Ws[r][c * 4 + 3] = w4.w;
    }
    __syncthreads();
    const int tx = tid & 31, my = tid >> 5;
    const float b = z2h_b[j0 + tx];
    #pragma unroll
    for (int mi = 0; mi < 4; mi++) {
        int m = my * 4 + mi;
        float acc = b;
        #pragma unroll 8
        for (int k = 0; k < DE; k++) acc = fmaf(Zs[m][k], Ws[tx][k], acc);
        int gm = m0 + m, gj = j0 + tx;
        g_H[0][0][gj][gm] = acc;
        g_H[0][1][gj][gm] = acc;
        g_H[0][2][gj][gm] = acc;
    }
}

// ---------------- cp.async stage of one 32-k chunk (A: [k][64m], W: [96 j][32 k]) ----------------
template <int DIN>
__device__ __forceinline__ void stage_chunk(uint32_t sb,
        const float* __restrict__ Xc, const float* __restrict__ Hc,
        const float* __restrict__ wih, const float* __restrict__ whh,
        int c, int m0, int j0, int tid) {
    const bool isX = (c < DIN / 32);
    const int kc = (isX ? c : c - DIN / 32) * 32;
    const float* asrc = isX ? Xc : Hc;          // column-major [feature][N_SEQ]
    const float* wsrc = isX ? wih : whh;        // row-major [1536][wstr]
    const int wstr = isX ? DIN : DH;
    #pragma unroll
    for (int q = 0; q < 2; q++) {               // A: 512 x 16B
        int idx = tid + q * 256;
        int k = idx >> 4, mseg = idx & 15;
        cp16(sb + (uint32_t)(k * PADM + mseg * 4) * 4,
             asrc + (size_t)(kc + k) * N_SEQ + m0 + mseg * 4);
    }
    #pragma unroll
    for (int q = 0; q < 3; q++) {               // W: 768 x 16B
        int idx = tid + q * 256;
        int row = idx >> 3, cc = idx & 7;       // row 0..95 = gate*32 + j
        int wrow = (row >> 5) * DH + j0 + (row & 31);
        cp16(sb + (uint32_t)A_BYTES + (uint32_t)(row * WPAD + cc * 4) * 4,
             wsrc + (size_t)wrow * wstr + kc + cc * 4);
    }
    CP_COMMIT();
}

// ---------------- fused GRU: 64m x 32j per block, 3 blocks/SM, f32x2, triple-buffer ----------------
// Per-output FMA chain = ascending k, identical values to R12 (bit-exact).
#define INNER(ACCN)                                                                   \
    do {                                                                              \
        _Pragma("unroll")                                                             \
        for (int k = 0; k < 32; k += 2) {                                             \
            float2 wrp = unpack2(*(const u64*)(Ws + (0 * 32 + tx) * WPAD + k));       \
            float2 wzp = unpack2(*(const u64*)(Ws + (32 + tx) * WPAD + k));           \
            float2 wnp = unpack2(*(const u64*)(Ws + (64 + tx) * WPAD + k));           \
            u64 wr0 = pack2(wrp.x), wr1 = pack2(wrp.y);                               \
            u64 wz0 = pack2(wzp.x), wz1 = pack2(wzp.y);                               \
            u64 wn0 = pack2(wnp.x), wn1 = pack2(wnp.y);                               \
            const u64* a0p = (const u64*)(As + k * PADM) + my * 4;                    \
            const u64* a1p = (const u64*)(As + (k + 1) * PADM) + my * 4;              \
            _Pragma("unroll")                                                         \
            for (int p = 0; p < 4; p++) {                                             \
                u64 a0 = a0p[p];                                                      \
                FMA2(accR[p], a0, wr0);                                               \
                FMA2(accZ[p], a0, wz0);                                               \
                FMA2(ACCN[p], a0, wn0);                                               \
                u64 a1 = a1p[p];                                                      \
                FMA2(accR[p], a1, wr1);                                               \
                FMA2(accZ[p], a1, wz1);                                               \
                FMA2(ACCN[p], a1, wn1);                                               \
            }                                                                         \
        }                                                                             \
    } while (0)

template <int DIN>
__global__ void __launch_bounds__(256, 3)
gru_kernel(int rb, int wb, int layer,
           const float* __restrict__ wih,   // [1536][DIN]
           const float* __restrict__ whh,   // [1536][512]
           const float* __restrict__ bih,
           const float* __restrict__ bhh) {
    extern __shared__ __align__(16) char smem[];
    const int m0 = blockIdx.x * 64;
    if (g_tdone[m0 >> 6] >= 64) return;

    const float* Xc = (DIN == DE) ? &g_X0[0][0] : &g_H[wb][layer - 1][0][0];
    const float* Hc = &g_H[rb][layer][0][0];
    float*       Ho = &g_H[wb][layer][0][0];

    const int j0 = blockIdx.y * 32;
    const int tid = threadIdx.x, tx = tid & 31, my = tid >> 5;
    const uint32_t sb0 = smem_u32(smem);

    u64 accR[4], accZ[4], accIN[4], accHN[4];
    #pragma unroll
    for (int p = 0; p < 4; p++) { accR[p] = 0; accZ[p] = 0; accIN[p] = 0; accHN[p] = 0; }

    const int nC = DIN / 32 + DH / 32;
    stage_chunk<DIN>(sb0,             Xc, Hc, wih, whh, 0, m0, j0, tid);
    stage_chunk<DIN>(sb0 + BUF_BYTES, Xc, Hc, wih, whh, 1, m0, j0, tid);

    // Triple buffer: single barrier per chunk (stage c+2 targets buf last read at c-1).
    #pragma unroll 1
    for (int c = 0; c < nC; c++) {
        if (c == nC - 1) { CP_WAIT0(); } else { CP_WAIT1(); }
        __syncthreads();
        const char* buf = smem + (size_t)(c % 3) * BUF_BYTES;
        const float* As = (const float*)buf;
        const float* Ws = (const float*)(buf + A_BYTES);
        if (c < DIN / 32) { INNER(accIN); } else { INNER(accHN); }
        if (c + 2 < nC)
            stage_chunk<DIN>(sb0 + (uint32_t)((c + 2) % 3) * BUF_BYTES,
                             Xc, Hc, wih, whh, c + 2, m0, j0, tid);
    }

    const int jj = j0 + tx;
    const float br  = bih[jj] + bhh[jj];
    const float bz  = bih[DH + jj] + bhh[DH + jj];
    const float bin = bih[2 * DH + jj];
    const float bhn = bhh[2 * DH + jj];
    #pragma unroll
    for (int p = 0; p < 4; p++) {
        float2 fr = unpack2(accR[p]), fz = unpack2(accZ[p]);
        float2 fi = unpack2(accIN[p]), fh = unpack2(accHN[p]);
        int m = m0 + my * 8 + 2 * p;
        {
            float rv = 1.f / (1.f + expf(-(fr.x + br)));
            float zv = 1.f / (1.f + expf(-(fz.x + bz)));
            float gv = tanhf(fi.x + bin + rv * (fh.x + bhn));
            float hp = Hc[(size_t)jj * N_SEQ + m];
            Ho[(size_t)jj * N_SEQ + m] = (1.f - zv) * gv + zv * hp;
        }
        {
            float rv = 1.f / (1.f + expf(-(fr.y + br)));
            float zv = 1.f / (1.f + expf(-(fz.y + bz)));
            float gv = tanhf(fi.y + bin + rv * (fh.y + bhn));
            float hp = Hc[(size_t)jj * N_SEQ + m + 1];
            Ho[(size_t)jj * N_SEQ + m + 1] = (1.f - zv) * gv + zv * hp;
        }
    }
}

// ---------------- head: logits GEMM + fused argmax/eos/embed (bit-exact vs R12) ----------------
__global__ void __launch_bounds__(256, 2)
head_gemm(int wb, const float* __restrict__ h2v_w, const float* __restrict__ h2v_b,
          const float* __restrict__ emb, float* __restrict__ Xgen, int t) {
    extern __shared__ __align__(16) char smem[];
    const int m0 = blockIdx.x * 128;
    if (g_tdone[m0 >> 6] + g_tdone[(m0 >> 6) + 1] >= 128) return;

    const float* Hc = &g_H[wb][2][0][0];        // col-major [DH][N_SEQ]
    const int tid = threadIdx.x, tx = tid & 31, my = tid >> 5;
    const uint32_t sb0 = smem_u32(smem);

    // acc0: v = tx, acc1: v = tx+32; init with bias
    u64 acc0[8], acc1[8];
    const u64 b0 = pack2(h2v_b[tx]), b1 = pack2(h2v_b[tx + 32]);
    #pragma unroll
    for (int p = 0; p < 8; p++) { acc0[p] = b0; acc1[p] = b1; }

    auto stage = [&](uint32_t sb, int c) {
        const int kc = c * 32;
        #pragma unroll
        for (int q = 0; q < 4; q++) {
            int idx = tid + q * 256;
            int k = idx >> 5, mseg = idx & 31;
            cp16(sb + (uint32_t)(k * HPADM + mseg * 4) * 4,
                 Hc + (size_t)(kc + k) * N_SEQ + m0 + mseg * 4);
        }
        #pragma unroll
        for (int q = 0; q < 2; q++) {
            int idx = tid + q * 256;
            int row = idx >> 3, cc = idx & 7;   // row = vocab 0..63
            cp16(sb + (uint32_t)HA_BYTES + (uint32_t)(row * WPAD + cc * 4) * 4,
                 h2v_w + (size_t)row * DH + kc + cc * 4);
        }
        CP_COMMIT();
    };

    stage(sb0, 0);
    stage(sb0 + HBUF_BYTES, 1);
    #pragma unroll 1
    for (int c = 0; c < 16; c++) {
        if (c == 15) { CP_WAIT0(); } else { CP_WAIT1(); }
        __syncthreads();
        const char* buf = smem + (size_t)(c & 1) * HBUF_BYTES;
        const float* As = (const float*)buf;
        const float* Ws = (const float*)(buf + HA_BYTES);
        #pragma unroll
        for (int k = 0; k < 32; k += 2) {
            float2 w0p = unpack2(*(const u64*)(Ws + tx * WPAD + k));
            float2 w1p = unpack2(*(const u64*)(Ws + (32 + tx) * WPAD + k));
            u64 w00 = pack2(w0p.x), w01 = pack2(w0p.y);
            u64 w10 = pack2(w1p.x), w11 = pack2(w1p.y);
            const u64* a0p = (const u64*)(As + k * HPADM) + my * 8;
            const u64* a1p = (const u64*)(As + (k + 1) * HPADM) + my * 8;
            #pragma unroll
            for (int p = 0; p < 8; p++) {
                u64 a0 = a0p[p];
                FMA2(acc0[p], a0, w00);
                FMA2(acc1[p], a0, w10);
                u64 a1 = a1p[p];
                FMA2(acc0[p], a1, w01);
                FMA2(acc1[p], a1, w11);
            }
        }
        __syncthreads();
        if (c + 2 < 16) stage(sb0 + (uint32_t)(c & 1) * HBUF_BYTES, c + 2);
    }

    // fused pick: lane tx holds vocab tx (acc0) and tx+32 (acc1)
    #pragma unroll 1
    for (int p = 0; p < 8; p++) {
        float2 f0 = unpack2(acc0[p]);
        float2 f1 = unpack2(acc1[p]);
        #pragma unroll 1
        for (int h = 0; h < 2; h++) {
            const int row = m0 + my * 16 + 2 * p + h;
            if (g_eos[row]) continue;              // finished: fin_kernel fills PAD
            float v0 = h ? f0.y : f0.x;
            float v1 = h ? f1.y : f1.x;
            float best; int bi;
            if (v1 > v0) { best = v1; bi = tx + 32; } else { best = v0; bi = tx; }
            #pragma unroll
            for (int off = 16; off > 0; off >>= 1) {
                float ov = __shfl_down_sync(0xffffffffu, best, off);
                int   oi = __shfl_down_sync(0xffffffffu, bi, off);
                if (ov > best || (ov == best && oi < bi)) { best = ov; bi = oi; }
            }
            int xt = __shfl_sync(0xffffffffu, bi, 0);
            if (tx == 0) {
                Xgen[row * TMAX + t] = (float)xt;
                if (xt == 2) {
                    g_eos[row] = 1;
                    g_first[row] = t;
                    atomicAdd(&g_tdone[row >> 6], 1);
                }
            }
            float4 e = ((const float4*)(emb + (size_t)xt * DE))[tx];
            g_X0[tx * 4 + 0][row] = e.x;
            g_X0[tx * 4 + 1][row] = e.y;
            g_X0[tx * 4 + 2][row] = e.z;
            g_X0[tx * 4 + 3][row] = e.w;
        }
    }
}

// ---------------- finalize: PAD tail after EOS + seq_lens ----------------
__global__ void fin_kernel(float* __restrict__ out, int out_size) {
    int i = blockIdx.x * 256 + threadIdx.x;
    if (i >= N_SEQ) return;
    int f = g_first[i];
    if (f) {
        for (int t = f + 1; t < TMAX; t++) out[i * TMAX + t] = 0.0f;
    }
    if (out_size >= N_SEQ * TMAX + N_SEQ)
        out[N_SEQ * TMAX + i] = (float)(f ? (f + 1) : TMAX);
}

// ---------------- launcher ----------------
extern "C" void kernel_launch(void* const* d_in, const int* in_sizes, int n_in,
                              void* d_out, int out_size) {
    (void)in_sizes; (void)n_in;
    const float* Z     = (const float*)d_in[0];
    const float* emb   = (const float*)d_in[1];
    const float* z2h_w = (const float*)d_in[2];
    const float* z2h_b = (const float*)d_in[3];
    const float* w_ih0 = (const float*)d_in[4];   // [1536][128]
    const float* w_ihr = (const float*)d_in[5];   // [2][1536][512]
    const float* w_hh  = (const float*)d_in[6];   // [3][1536][512]
    const float* b_ih  = (const float*)d_in[7];   // [3][1536]
    const float* b_hh  = (const float*)d_in[8];
    const float* h2v_w = (const float*)d_in[9];   // [64][512]
    const float* h2v_b = (const float*)d_in[10];  // [64]
    float* out = (float*)d_out;

    cudaFuncSetAttribute(gru_kernel<DE>, cudaFuncAttributeMaxDynamicSharedMemorySize, GRU_SMEM);
    cudaFuncSetAttribute(gru_kernel<DH>, cudaFuncAttributeMaxDynamicSharedMemorySize, GRU_SMEM);
    cudaFuncSetAttribute(head_gemm, cudaFuncAttributeMaxDynamicSharedMemorySize, HEAD_SMEM);

    init_kernel<<<(N_SEQ * 32) / 256, 256>>>(emb, out);
    h0_kernel<<<dim3(N_SEQ / 32, DH / 32), 256>>>(Z, z2h_w, z2h_b);

    const size_t WL = (size_t)G3 * DH;            // per-layer w_hh / w_ih_rest slab
    const dim3 ggrid(N_SEQ / 64, DH / 32);        // 128 x 16 = 2048 blocks

    for (int t = 1; t < TMAX; t++) {
        const int rb = (t - 1) & 1, wb = t & 1;
        gru_kernel<DE><<<ggrid, 256, GRU_SMEM>>>(rb, wb, 0, w_ih0,      w_hh,          b_ih,          b_hh);
        gru_kernel<DH><<<ggrid, 256, GRU_SMEM>>>(rb, wb, 1, w_ihr,      w_hh + WL,     b_ih + G3,     b_hh + G3);
        gru_kernel<DH><<<ggrid, 256, GRU_SMEM>>>(rb, wb, 2, w_ihr + WL, w_hh + 2 * WL, b_ih + 2 * G3, b_hh + 2 * G3);
        head_gemm<<<N_SEQ / 128, 256, HEAD_SMEM>>>(wb, h2v_w, h2v_b, emb, out, t);
    }
    fin_kernel<<<N_SEQ / 256, 256>>>(out, out_size);
}

// round 14
// speedup vs baseline: 1.0582x; 1.0582x over previous
#include <cuda_runtime.h>
#include <cstdint>

#define N_SEQ 8192
#define DH    512
#define DE    128
#define TMAX  80
#define G3    1536

#define PADM 132                       // A-tile float stride (16B-aligned rows, even)
#define WPAD 36                        // W-tile float stride (16B-aligned, even)
#define A_BYTES (32 * PADM * 4)        // 16896
#define W_BYTES (96 * WPAD * 4)        // 13824
#define BUF_BYTES (A_BYTES + W_BYTES)  // 30720
#define GRU_SMEM (3 * BUF_BYTES)       // 92160 (triple buffer)

#define HW_BYTES (64 * WPAD * 4)           // 9216 (head W tile)
#define HBUF_BYTES (A_BYTES + HW_BYTES)    // 26112
#define HEAD_SMEM (2 * HBUF_BYTES)         // 52224

typedef unsigned long long u64;

// ---------------- device-global state (module-static, no runtime allocation) ----------------
// COLUMN-MAJOR hidden state: [buf][layer][feature][row] so A-tiles are cp.async-contiguous.
__device__ __align__(16) float g_H[2][3][DH][N_SEQ];
__device__ __align__(16) float g_X0[DE][N_SEQ];        // embedded previous token, col-major
__device__ int g_eos[N_SEQ];
__device__ int g_first[N_SEQ];
__device__ int g_tdone[N_SEQ / 128];

// ---------------- helpers ----------------
__device__ __forceinline__ uint32_t smem_u32(const void* p) {
    uint32_t a;
    asm("{ .reg .u64 t; cvta.to.shared.u64 t, %1; cvt.u32.u64 %0, t; }" : "=r"(a) : "l"(p));
    return a;
}
__device__ __forceinline__ u64 pack2(float x) {
    u64 r;
    asm("mov.b64 %0, {%1, %1};" : "=l"(r) : "f"(x));
    return r;
}
__device__ __forceinline__ float2 unpack2(u64 v) {
    float lo, hi;
    asm("mov.b64 {%0, %1}, %2;" : "=f"(lo), "=f"(hi) : "l"(v));
    return make_float2(lo, hi);
}
#define FMA2(acc, a, w) \
    asm("fma.rn.f32x2 %0, %1, %2, %0;" : "+l"(acc) : "l"(a), "l"(w))

__device__ __forceinline__ void cp16(uint32_t dst, const void* src) {
    asm volatile("cp.async.cg.shared.global [%0], [%1], 16;" :: "r"(dst), "l"(src));
}
#define CP_COMMIT() asm volatile("cp.async.commit_group;" ::: "memory")
#define CP_WAIT0()  asm volatile("cp.async.wait_group 0;" ::: "memory")
#define CP_WAIT1()  asm volatile("cp.async.wait_group 1;" ::: "memory")

// ---------------- init: eos=0, X_gen col0 = SOS, X0 = emb[SOS] (col-major) ----------------
__global__ void init_kernel(const float* __restrict__ emb, float* __restrict__ Xgen) {
    int t = blockIdx.x * 256 + threadIdx.x;   // N_SEQ*32 threads
    int row = t >> 5, lane = t & 31;
    if (row >= N_SEQ) return;
    float4 e = ((const float4*)(emb + 1 * DE))[lane];
    g_X0[lane * 4 + 0][row] = e.x;
    g_X0[lane * 4 + 1][row] = e.y;
    g_X0[lane * 4 + 2][row] = e.z;
    g_X0[lane * 4 + 3][row] = e.w;
    if (lane == 0) {
        g_eos[row]   = 0;
        g_first[row] = 0;
        Xgen[row * TMAX] = 1.0f;   // SOS (output buffer is float32)
        if (row < N_SEQ / 128) g_tdone[row] = 0;
    }
}

// ---------------- h0 = Z @ z2h_w^T + b, replicated to 3 layers of buffer 0 (col-major) ----------------
__global__ void __launch_bounds__(256)
h0_kernel(const float* __restrict__ Z, const float* __restrict__ z2h_w,
          const float* __restrict__ z2h_b) {
    __shared__ __align__(16) float Zs[32][DE];
    __shared__ __align__(16) float Ws[32][DE + 1];
    const int m0 = blockIdx.x * 32, j0 = blockIdx.y * 32;
    const int tid = threadIdx.x;
    for (int i = tid; i < 32 * (DE / 4); i += 256) {
        int r = i >> 5, c = i & 31;
        float4 z4 = ((const float4*)(Z + (size_t)(m0 + r) * DE))[c];
        Zs[r][c * 4 + 0] = z4.x; Zs[r][c * 4 + 1] = z4.y;
        Zs[r][c * 4 + 2] = z4.z; Zs[r][c * 4 + 3] = z4.w;
        float4 w4 = ((const float4*)(z2h_w + (size_t)(j0 + r) * DE))[c];
        Ws[r][c * 4 + 0] = w4.x; Ws[r][c * 4 + 1] = w4.y;
        Ws[r][c * 4 + 2] = w4.z; Ws[r][c * 4 + 3] = w4.w;
    }
    __syncthreads();
    const int tx = tid & 31, my = tid >> 5;
    const float b = z2h_b[j0 + tx];
    #pragma unroll
    for (int mi = 0; mi < 4; mi++) {
        int m = my * 4 + mi;
        float acc = b;
        #pragma unroll 8
        for (int k = 0; k < DE; k++) acc = fmaf(Zs[m][k], Ws[tx][k], acc);
        int gm = m0 + m, gj = j0 + tx;
        g_H[0][0][gj][gm] = acc;
        g_H[0][1][gj][gm] = acc;
        g_H[0][2][gj][gm] = acc;
    }
}

// ---------------- cp.async stage of one 32-k chunk (A: [k][128m], W: [96 j][32 k]) ----------------
template <int DIN>
__device__ __forceinline__ void stage_chunk(uint32_t sb,
        const float* __restrict__ Xc, const float* __restrict__ Hc,
        const float* __restrict__ wih, const float* __restrict__ whh,
        int c, int m0, int j0, int tid) {
    const bool isX = (c < DIN / 32);
    const int kc = (isX ? c : c - DIN / 32) * 32;
    const float* asrc = isX ? Xc : Hc;          // column-major [feature][N_SEQ]
    const float* wsrc = isX ? wih : whh;        // row-major [1536][wstr]
    const int wstr = isX ? DIN : DH;
    #pragma unroll
    for (int q = 0; q < 4; q++) {               // A: 1024 x 16B
        int idx = tid + q * 256;
        int k = idx >> 5, mseg = idx & 31;
        cp16(sb + (uint32_t)(k * PADM + mseg * 4) * 4,
             asrc + (size_t)(kc + k) * N_SEQ + m0 + mseg * 4);
    }
    #pragma unroll
    for (int q = 0; q < 3; q++) {               // W: 768 x 16B
        int idx = tid + q * 256;
        int row = idx >> 3, cc = idx & 7;       // row 0..95 = gate*32 + j
        int wrow = (row >> 5) * DH + j0 + (row & 31);
        cp16(sb + (uint32_t)A_BYTES + (uint32_t)(row * WPAD + cc * 4) * 4,
             wsrc + (size_t)wrow * wstr + kc + cc * 4);
    }
    CP_COMMIT();
}

// ---------------- fused GRU: 128m x 32j per block, f32x2 FMA, cp.async TRIPLE-buffer ----------------
// Same values/chain order as R12 (bit-exact); A reads widened to LDS.128.
#define INNER(ACCN)                                                                   \
    do {                                                                              \
        _Pragma("unroll")                                                             \
        for (int k = 0; k < 32; k += 2) {                                             \
            float2 wrp = unpack2(*(const u64*)(Ws + (0 * 32 + tx) * WPAD + k));       \
            float2 wzp = unpack2(*(const u64*)(Ws + (32 + tx) * WPAD + k));           \
            float2 wnp = unpack2(*(const u64*)(Ws + (64 + tx) * WPAD + k));           \
            u64 wr0 = pack2(wrp.x), wr1 = pack2(wrp.y);                               \
            u64 wz0 = pack2(wzp.x), wz1 = pack2(wzp.y);                               \
            u64 wn0 = pack2(wnp.x), wn1 = pack2(wnp.y);                               \
            const ulonglong2* a0p = (const ulonglong2*)(As + k * PADM) + my * 4;      \
            const ulonglong2* a1p = (const ulonglong2*)(As + (k + 1) * PADM) + my * 4;\
            _Pragma("unroll")                                                         \
            for (int q = 0; q < 4; q++) {                                             \
                ulonglong2 a0v = a0p[q];                                              \
                ulonglong2 a1v = a1p[q];                                              \
                FMA2(accR[2 * q], a0v.x, wr0);                                        \
                FMA2(accZ[2 * q], a0v.x, wz0);                                        \
                FMA2(ACCN[2 * q], a0v.x, wn0);                                        \
                FMA2(accR[2 * q + 1], a0v.y, wr0);                                    \
                FMA2(accZ[2 * q + 1], a0v.y, wz0);                                    \
                FMA2(ACCN[2 * q + 1], a0v.y, wn0);                                    \
                FMA2(accR[2 * q], a1v.x, wr1);                                        \
                FMA2(accZ[2 * q], a1v.x, wz1);                                        \
                FMA2(ACCN[2 * q], a1v.x, wn1);                                        \
                FMA2(accR[2 * q + 1], a1v.y, wr1);                                    \
                FMA2(accZ[2 * q + 1], a1v.y, wz1);                                    \
                FMA2(ACCN[2 * q + 1], a1v.y, wn1);                                    \
            }                                                                         \
        }                                                                             \
    } while (0)

template <int DIN>
__global__ void __launch_bounds__(256, 2)
gru_kernel(int rb, int wb, int layer,
           const float* __restrict__ wih,   // [1536][DIN]
           const float* __restrict__ whh,   // [1536][512]
           const float* __restrict__ bih,
           const float* __restrict__ bhh) {
    extern __shared__ __align__(16) char smem[];
    const int m0 = blockIdx.x * 128;
    if (g_tdone[m0 >> 7] >= 128) return;

    const float* Xc = (DIN == DE) ? &g_X0[0][0] : &g_H[wb][layer - 1][0][0];
    const float* Hc = &g_H[rb][layer][0][0];
    float*       Ho = &g_H[wb][layer][0][0];

    const int j0 = blockIdx.y * 32;
    const int tid = threadIdx.x, tx = tid & 31, my = tid >> 5;
    const uint32_t sb0 = smem_u32(smem);

    u64 accR[8], accZ[8], accIN[8], accHN[8];
    #pragma unroll
    for (int p = 0; p < 8; p++) { accR[p] = 0; accZ[p] = 0; accIN[p] = 0; accHN[p] = 0; }

    const int nC = DIN / 32 + DH / 32;
    stage_chunk<DIN>(sb0,             Xc, Hc, wih, whh, 0, m0, j0, tid);
    stage_chunk<DIN>(sb0 + BUF_BYTES, Xc, Hc, wih, whh, 1, m0, j0, tid);

    // Triple buffer: single barrier per chunk (stage c+2 targets buf last read at c-1).
    #pragma unroll 1
    for (int c = 0; c < nC; c++) {
        if (c == nC - 1) { CP_WAIT0(); } else { CP_WAIT1(); }
        __syncthreads();
        const char* buf = smem + (size_t)(c % 3) * BUF_BYTES;
        const float* As = (const float*)buf;
        const float* Ws = (const float*)(buf + A_BYTES);
        if (c < DIN / 32) { INNER(accIN); } else { INNER(accHN); }
        if (c + 2 < nC)
            stage_chunk<DIN>(sb0 + (uint32_t)((c + 2) % 3) * BUF_BYTES,
                             Xc, Hc, wih, whh, c + 2, m0, j0, tid);
    }

    const int jj = j0 + tx;
    const float br  = bih[jj] + bhh[jj];
    const float bz  = bih[DH + jj] + bhh[DH + jj];
    const float bin = bih[2 * DH + jj];
    const float bhn = bhh[2 * DH + jj];
    #pragma unroll
    for (int p = 0; p < 8; p++) {
        float2 fr = unpack2(accR[p]), fz = unpack2(accZ[p]);
        float2 fi = unpack2(accIN[p]), fh = unpack2(accHN[p]);
        int m = m0 + my * 16 + 2 * p;
        {
            float rv = 1.f / (1.f + expf(-(fr.x + br)));
            float zv = 1.f / (1.f + expf(-(fz.x + bz)));
            float gv = tanhf(fi.x + bin + rv * (fh.x + bhn));
            float hp = Hc[(size_t)jj * N_SEQ + m];
            Ho[(size_t)jj * N_SEQ + m] = (1.f - zv) * gv + zv * hp;
        }
        {
            float rv = 1.f / (1.f + expf(-(fr.y + br)));
            float zv = 1.f / (1.f + expf(-(fz.y + bz)));
            float gv = tanhf(fi.y + bin + rv * (fh.y + bhn));
            float hp = Hc[(size_t)jj * N_SEQ + m + 1];
            Ho[(size_t)jj * N_SEQ + m + 1] = (1.f - zv) * gv + zv * hp;
        }
    }
}

// ---------------- head: logits GEMM + fused argmax/eos/embed (bit-exact vs R12) ----------------
__global__ void __launch_bounds__(256, 2)
head_gemm(int wb, const float* __restrict__ h2v_w, const float* __restrict__ h2v_b,
          const float* __restrict__ emb, float* __restrict__ Xgen, int t) {
    extern __shared__ __align__(16) char smem[];
    const int m0 = blockIdx.x * 128;
    if (g_tdone[m0 >> 7] >= 128) return;

    const float* Hc = &g_H[wb][2][0][0];        // col-major [DH][N_SEQ]
    const int tid = threadIdx.x, tx = tid & 31, my = tid >> 5;
    const uint32_t sb0 = smem_u32(smem);

    // acc0: v = tx, acc1: v = tx+32; init with bias (same chain as R12)
    u64 acc0[8], acc1[8];
    const u64 b0 = pack2(h2v_b[tx]), b1 = pack2(h2v_b[tx + 32]);
    #pragma unroll
    for (int p = 0; p < 8; p++) { acc0[p] = b0; acc1[p] = b1; }

    auto stage = [&](uint32_t sb, int c) {
        const int kc = c * 32;
        #pragma unroll
        for (int q = 0; q < 4; q++) {
            int idx = tid + q * 256;
            int k = idx >> 5, mseg = idx & 31;
            cp16(sb + (uint32_t)(k * PADM + mseg * 4) * 4,
                 Hc + (size_t)(kc + k) * N_SEQ + m0 + mseg * 4);
        }
        #pragma unroll
        for (int q = 0; q < 2; q++) {
            int idx = tid + q * 256;
            int row = idx >> 3, cc = idx & 7;   // row = vocab 0..63
            cp16(sb + (uint32_t)A_BYTES + (uint32_t)(row * WPAD + cc * 4) * 4,
                 h2v_w + (size_t)row * DH + kc + cc * 4);
        }
        CP_COMMIT();
    };

    stage(sb0, 0);
    stage(sb0 + HBUF_BYTES, 1);
    #pragma unroll 1
    for (int c = 0; c < 16; c++) {
        if (c == 15) { CP_WAIT0(); } else { CP_WAIT1(); }
        __syncthreads();
        const char* buf = smem + (size_t)(c & 1) * HBUF_BYTES;
        const float* As = (const float*)buf;
        const float* Ws = (const float*)(buf + A_BYTES);
        #pragma unroll
        for (int k = 0; k < 32; k += 2) {
            float2 w0p = unpack2(*(const u64*)(Ws + tx * WPAD + k));
            float2 w1p = unpack2(*(const u64*)(Ws + (32 + tx) * WPAD + k));
            u64 w00 = pack2(w0p.x), w01 = pack2(w0p.y);
            u64 w10 = pack2(w1p.x), w11 = pack2(w1p.y);
            const u64* a0p = (const u64*)(As + k * PADM) + my * 8;
            const u64* a1p = (const u64*)(As + (k + 1) * PADM) + my * 8;
            #pragma unroll
            for (int p = 0; p < 8; p++) {
                u64 a0 = a0p[p];
                FMA2(acc0[p], a0, w00);
                FMA2(acc1[p], a0, w10);
                u64 a1 = a1p[p];
                FMA2(acc0[p], a1, w01);
                FMA2(acc1[p], a1, w11);
            }
        }
        __syncthreads();
        if (c + 2 < 16) stage(sb0 + (uint32_t)(c & 1) * HBUF_BYTES, c + 2);
    }

    // fused pick: lane tx holds vocab tx (acc0) and tx+32 (acc1)
    #pragma unroll 1
    for (int p = 0; p < 8; p++) {
        float2 f0 = unpack2(acc0[p]);
        float2 f1 = unpack2(acc1[p]);
        #pragma unroll 1
        for (int h = 0; h < 2; h++) {
            const int row = m0 + my * 16 + 2 * p + h;
            if (g_eos[row]) continue;              // finished: fin_kernel fills PAD
            float v0 = h ? f0.y : f0.x;
            float v1 = h ? f1.y : f1.x;
            float best; int bi;
            if (v1 > v0) { best = v1; bi = tx + 32; } else { best = v0; bi = tx; }
            #pragma unroll
            for (int off = 16; off > 0; off >>= 1) {
                float ov = __shfl_down_sync(0xffffffffu, best, off);
                int   oi = __shfl_down_sync(0xffffffffu, bi, off);
                if (ov > best || (ov == best && oi < bi)) { best = ov; bi = oi; }
            }
            int xt = __shfl_sync(0xffffffffu, bi, 0);
            if (tx == 0) {
                Xgen[row * TMAX + t] = (float)xt;
                if (xt == 2) {
                    g_eos[row] = 1;
                    g_first[row] = t;
                    atomicAdd(&g_tdone[row >> 7], 1);
                }
            }
            float4 e = ((const float4*)(emb + (size_t)xt * DE))[tx];
            g_X0[tx * 4 + 0][row] = e.x;
            g_X0[tx * 4 + 1][row] = e.y;
            g_X0[tx * 4 + 2][row] = e.z;
            g_X0[tx * 4 + 3][row] = e.w;
        }
    }
}

// ---------------- finalize: PAD tail after EOS + seq_lens ----------------
__global__ void fin_kernel(float* __restrict__ out, int out_size) {
    int i = blockIdx.x * 256 + threadIdx.x;
    if (i >= N_SEQ) return;
    int f = g_first[i];
    if (f) {
        for (int t = f + 1; t < TMAX; t++) out[i * TMAX + t] = 0.0f;
    }
    if (out_size >= N_SEQ * TMAX + N_SEQ)
        out[N_SEQ * TMAX + i] = (float)(f ? (f + 1) : TMAX);
}

// ---------------- launcher ----------------
extern "C" void kernel_launch(void* const* d_in, const int* in_sizes, int n_in,
                              void* d_out, int out_size) {
    (void)in_sizes; (void)n_in;
    const float* Z     = (const float*)d_in[0];
    const float* emb   = (const float*)d_in[1];
    const float* z2h_w = (const float*)d_in[2];
    const float* z2h_b = (const float*)d_in[3];
    const float* w_ih0 = (const float*)d_in[4];   // [1536][128]
    const float* w_ihr = (const float*)d_in[5];   // [2][1536][512]
    const float* w_hh  = (const float*)d_in[6];   // [3][1536][512]
    const float* b_ih  = (const float*)d_in[7];   // [3][1536]
    const float* b_hh  = (const float*)d_in[8];
    const float* h2v_w = (const float*)d_in[9];   // [64][512]
    const float* h2v_b = (const float*)d_in[10];  // [64]
    float* out = (float*)d_out;

    cudaFuncSetAttribute(gru_kernel<DE>, cudaFuncAttributeMaxDynamicSharedMemorySize, GRU_SMEM);
    cudaFuncSetAttribute(gru_kernel<DH>, cudaFuncAttributeMaxDynamicSharedMemorySize, GRU_SMEM);
    cudaFuncSetAttribute(head_gemm, cudaFuncAttributeMaxDynamicSharedMemorySize, HEAD_SMEM);

    init_kernel<<<(N_SEQ * 32) / 256, 256>>>(emb, out);
    h0_kernel<<<dim3(N_SEQ / 32, DH / 32), 256>>>(Z, z2h_w, z2h_b);

    const size_t WL = (size_t)G3 * DH;            // per-layer w_hh / w_ih_rest slab
    const dim3 ggrid(N_SEQ / 128, DH / 32);

    for (int t = 1; t < TMAX; t++) {
        const int rb = (t - 1) & 1, wb = t & 1;
        gru_kernel<DE><<<ggrid, 256, GRU_SMEM>>>(rb, wb, 0, w_ih0,      w_hh,          b_ih,          b_hh);
        gru_kernel<DH><<<ggrid, 256, GRU_SMEM>>>(rb, wb, 1, w_ihr,      w_hh + WL,     b_ih + G3,     b_hh + G3);
        gru_kernel<DH><<<ggrid, 256, GRU_SMEM>>>(rb, wb, 2, w_ihr + WL, w_hh + 2 * WL, b_ih + 2 * G3, b_hh + 2 * G3);
        head_gemm<<<N_SEQ / 128, 256, HEAD_SMEM>>>(wb, h2v_w, h2v_b, emb, out, t);
    }
    fin_kernel<<<N_SEQ / 256, 256>>>(out, out_size);
}